// round 1
// baseline (speedup 1.0000x reference)
#include <cuda_runtime.h>
#include <cstddef>

// Problem shape (fixed by the dataset):
//   feature_maps: (32, 256, 64, 64) f32   -> d_in[0]
//   anchors:      (32, 2048, 2)    f32    -> d_in[1]
//   out:          (32, 2048, 256)  f32
#define NB      32
#define NC      256
#define HH      64
#define HWSZ    4096          // 64*64
#define NANCH   2048
#define CPB     8             // channels per block
#define THREADS 512
#define PLANE   4100          // 4096 + 4-float pad: keeps 16B alignment, puts the
                              // 8 channel lanes of one anchor on distinct banks
                              // (4100 % 32 == 4 -> bank offset 4*c, c in [0,8))

__global__ __launch_bounds__(THREADS, 1)
void interp_gather_kernel(const float* __restrict__ fm,
                          const float* __restrict__ anchors,
                          float* __restrict__ out)
{
    extern __shared__ float smem[];
    float*  planes = smem;                                  // CPB * PLANE floats
    float4* meta   = (float4*)(smem + CPB * PLANE);         // NANCH float4

    const int tid = threadIdx.x;
    const int b   = blockIdx.y;
    const int c0  = blockIdx.x * CPB;

    // ---- Stage 8 spatial planes (8 * 16 KB) into SMEM, fully coalesced ----
    // Each plane is contiguous 4096 floats in gmem; read as float4.
    const float4* src = (const float4*)(fm + ((size_t)b * NC + c0) * HWSZ);
    #pragma unroll
    for (int k = 0; k < (CPB * HWSZ / 4) / THREADS; k++) {   // 16 iters
        int i = tid + k * THREADS;
        int c = i >> 10;            // / 1024 (float4 per plane)
        int j = i & 1023;
        float4 v = src[c * (HWSZ / 4) + j];
        *(float4*)&planes[c * PLANE + 4 * j] = v;            // c*PLANE%4==0 -> 16B aligned
    }

    // ---- Per-anchor metadata prepass (computed once per block) ----
    // meta = { dx, dy, bits(i00), bits(dxi | (dyi<<8)) }
    const float2* anc = (const float2*)(anchors + (size_t)b * NANCH * 2);
    #pragma unroll
    for (int k = 0; k < NANCH / THREADS; k++) {              // 4 iters
        int n = tid + k * THREADS;
        float2 a = anc[n];
        // pa = clip(a * (H-1), 0, H-1)
        float px = fminf(fmaxf(a.x * 63.0f, 0.0f), 63.0f);
        float py = fminf(fmaxf(a.y * 63.0f, 0.0f), 63.0f);
        float fx = floorf(px), fy = floorf(py);
        int ix = (int)fx, iy = (int)fy;
        int dxi = (int)ceilf(px) - ix;                       // 0 or 1
        int dyi = ((int)ceilf(py) - iy) << 6;                // 0 or 64
        int i00 = iy * HH + ix;
        meta[n] = make_float4(px - fx, py - fy,
                              __int_as_float(i00),
                              __int_as_float(dxi | (dyi << 8)));
    }
    __syncthreads();

    // ---- Gather + blend from SMEM ----
    // Warp layout: c = tid & 7 (channel), la = tid >> 3 (anchor lane).
    // Per anchor a warp's 8 channel lanes write 8 consecutive floats = one
    // full, aligned 32B sector of out[b, n, c0:c0+8].
    const int c  = tid & (CPB - 1);
    const int la = tid >> 3;                                 // 0..63
    const float* plane = planes + c * PLANE;
    float* op = out + (size_t)b * NANCH * NC + c0 + c;

    #pragma unroll 4
    for (int k = 0; k < NANCH / (THREADS / CPB); k++) {      // 32 iters
        int n = la + k * (THREADS / CPB);
        float4 m = meta[n];                                  // broadcast over 8 lanes
        int i00 = __float_as_int(m.z);
        int pk  = __float_as_int(m.w);
        int dxi = pk & 0xFF;                                 // 0/1
        int dyi = pk >> 8;                                   // 0/64
        float v00 = plane[i00];
        float v01 = plane[i00 + dxi];
        float v10 = plane[i00 + dyi];
        float v11 = plane[i00 + dyi + dxi];
        // exact reference blend order:
        float t  = v00 + (v01 - v00) * m.x;
        float bo = v10 + (v11 - v10) * m.x;
        op[(size_t)n * NC] = t + (bo - t) * m.y;
    }
}

extern "C" void kernel_launch(void* const* d_in, const int* in_sizes, int n_in,
                              void* d_out, int out_size)
{
    const float* fm  = (const float*)d_in[0];
    const float* anc = (const float*)d_in[1];
    float* out       = (float*)d_out;

    const size_t smem_bytes = (size_t)CPB * PLANE * sizeof(float)
                            + (size_t)NANCH * sizeof(float4);   // 163,968 B

    cudaFuncSetAttribute(interp_gather_kernel,
                         cudaFuncAttributeMaxDynamicSharedMemorySize,
                         (int)smem_bytes);

    dim3 grid(NC / CPB, NB);   // (32, 32) = 1024 blocks
    interp_gather_kernel<<<grid, THREADS, smem_bytes>>>(fm, anc, out);
}